// round 1
// baseline (speedup 1.0000x reference)
#include <cuda_runtime.h>
#include <cstdint>

// Problem constants
#define NB   32
#define LQ   2048
#define LK   2048
#define DIN  32
#define DKQ  20
#define EPS  1e-5f
#define INV_SQRT_DKQ 0.223606797749979f  // 1/sqrt(20)

// Scratch (allocation-free rule: __device__ globals)
__device__ float d_vproj[(size_t)NB * LK * DIN];   // [B,LK,32]
__device__ float d_kproj[(size_t)NB * LK * DKQ];   // [B,LK,20], LayerNormed
__device__ float d_qproj[(size_t)NB * LQ * DKQ];   // [B,LQ,20], LayerNormed, pre-scaled by 1/sqrt(20)

typedef unsigned long long u64;

__device__ __forceinline__ u64 pack2(float lo, float hi) {
    u64 r; asm("mov.b64 %0, {%1, %2};" : "=l"(r) : "f"(lo), "f"(hi)); return r;
}
__device__ __forceinline__ float2 unpack2(u64 v) {
    float2 f; asm("mov.b64 {%0, %1}, %2;" : "=f"(f.x), "=f"(f.y) : "l"(v)); return f;
}
// Packed dual-FMA: d = a*b + c elementwise on two fp32 lanes (sm_100+/sm_103a)
__device__ __forceinline__ u64 ffma2(u64 a, u64 b, u64 c) {
    u64 d; asm("fma.rn.f32x2 %0, %1, %2, %3;" : "=l"(d) : "l"(a), "l"(b), "l"(c)); return d;
}

// ---------------------------------------------------------------------------
// Kernel 1: fused projections  v = vals@Wv^T ; k = LN(keys@Wk^T) ; q = LN(ques@Wq^T)/sqrt(20)
// One thread per row (B*2048 rows).
// ---------------------------------------------------------------------------
__global__ __launch_bounds__(256) void proj_kernel(
    const float* __restrict__ vals, const float* __restrict__ keys,
    const float* __restrict__ ques,
    const float* __restrict__ Wv, const float* __restrict__ Wk, const float* __restrict__ Wq,
    const float* __restrict__ gk, const float* __restrict__ bk,
    const float* __restrict__ gq, const float* __restrict__ bq)
{
    __shared__ float sWv[DIN * DIN];
    __shared__ float sWk[DKQ * DIN];
    __shared__ float sWq[DKQ * DIN];
    __shared__ float sgk[DKQ], sbk[DKQ], sgq[DKQ], sbq[DKQ];

    int tid = threadIdx.x;
    for (int i = tid; i < DIN * DIN; i += 256) sWv[i] = Wv[i];
    for (int i = tid; i < DKQ * DIN; i += 256) sWk[i] = Wk[i];
    for (int i = tid; i < DKQ * DIN; i += 256) sWq[i] = Wq[i];
    if (tid < DKQ) { sgk[tid] = gk[tid]; sbk[tid] = bk[tid]; sgq[tid] = gq[tid]; sbq[tid] = bq[tid]; }
    __syncthreads();

    size_t r = (size_t)blockIdx.x * 256 + tid;   // row in [0, B*2048)

    float x[DIN];

    // ---- V projection ----
    {
        const float4* p4 = (const float4*)(vals + r * DIN);
        #pragma unroll
        for (int i = 0; i < 8; i++) {
            float4 t = p4[i];
            x[4*i] = t.x; x[4*i+1] = t.y; x[4*i+2] = t.z; x[4*i+3] = t.w;
        }
        float outr[DIN];
        #pragma unroll
        for (int o = 0; o < DIN; o++) {
            float acc = 0.f;
            #pragma unroll
            for (int d = 0; d < DIN; d++) acc += x[d] * sWv[o * DIN + d];
            outr[o] = acc;
        }
        float4* o4 = (float4*)(d_vproj + r * DIN);
        #pragma unroll
        for (int i = 0; i < 8; i++)
            o4[i] = make_float4(outr[4*i], outr[4*i+1], outr[4*i+2], outr[4*i+3]);
    }

    // ---- K projection + LN ----
    {
        const float4* p4 = (const float4*)(keys + r * DIN);
        #pragma unroll
        for (int i = 0; i < 8; i++) {
            float4 t = p4[i];
            x[4*i] = t.x; x[4*i+1] = t.y; x[4*i+2] = t.z; x[4*i+3] = t.w;
        }
        float y[DKQ];
        #pragma unroll
        for (int o = 0; o < DKQ; o++) {
            float acc = 0.f;
            #pragma unroll
            for (int d = 0; d < DIN; d++) acc += x[d] * sWk[o * DIN + d];
            y[o] = acc;
        }
        float m = 0.f;
        #pragma unroll
        for (int c = 0; c < DKQ; c++) m += y[c];
        m *= (1.f / DKQ);
        float v = 0.f;
        #pragma unroll
        for (int c = 0; c < DKQ; c++) { float d = y[c] - m; v += d * d; }
        v *= (1.f / DKQ);
        float rs = rsqrtf(v + EPS);
        #pragma unroll
        for (int c = 0; c < DKQ; c++) y[c] = (y[c] - m) * rs * sgk[c] + sbk[c];
        float4* o4 = (float4*)(d_kproj + r * DKQ);
        #pragma unroll
        for (int i = 0; i < 5; i++)
            o4[i] = make_float4(y[4*i], y[4*i+1], y[4*i+2], y[4*i+3]);
    }

    // ---- Q projection + LN + prescale ----
    {
        const float4* p4 = (const float4*)(ques + r * DIN);
        #pragma unroll
        for (int i = 0; i < 8; i++) {
            float4 t = p4[i];
            x[4*i] = t.x; x[4*i+1] = t.y; x[4*i+2] = t.z; x[4*i+3] = t.w;
        }
        float y[DKQ];
        #pragma unroll
        for (int o = 0; o < DKQ; o++) {
            float acc = 0.f;
            #pragma unroll
            for (int d = 0; d < DIN; d++) acc += x[d] * sWq[o * DIN + d];
            y[o] = acc;
        }
        float m = 0.f;
        #pragma unroll
        for (int c = 0; c < DKQ; c++) m += y[c];
        m *= (1.f / DKQ);
        float v = 0.f;
        #pragma unroll
        for (int c = 0; c < DKQ; c++) { float d = y[c] - m; v += d * d; }
        v *= (1.f / DKQ);
        float rs = rsqrtf(v + EPS);
        #pragma unroll
        for (int c = 0; c < DKQ; c++)
            y[c] = ((y[c] - m) * rs * sgq[c] + sbq[c]) * INV_SQRT_DKQ;
        float4* o4 = (float4*)(d_qproj + r * DKQ);
        #pragma unroll
        for (int i = 0; i < 5; i++)
            o4[i] = make_float4(y[4*i], y[4*i+1], y[4*i+2], y[4*i+3]);
    }
}

// ---------------------------------------------------------------------------
// Kernel 2: fused attention (no-max softmax, bounded scores) + residual LN
// 128 threads/block, 2 queries/thread -> 256 queries/block. grid = (8, 32).
// Packed f32x2 FMA: the score chain evaluates both queries simultaneously;
// K stored DUPLICATED in smem so LDS.128 yields ready (k,k) packed operands.
// ---------------------------------------------------------------------------
#define TS 128

__global__ __launch_bounds__(128) void attn_kernel(
    const void* __restrict__ mask_raw, const float* __restrict__ ques,
    const float* __restrict__ go, const float* __restrict__ bo,
    float* __restrict__ out)
{
    __shared__ float ks2[TS * 2 * DKQ];   // duplicated K tile: [key][2*c]
    __shared__ float vs[TS * DIN];
    __shared__ float ms[TS];
    __shared__ float sgo[DIN], sbo[DIN];
    __shared__ int s_is_byte;

    int tid = threadIdx.x;
    int b   = blockIdx.y;

    if (tid < DIN) { sgo[tid] = go[tid]; sbo[tid] = bo[tid]; }
    if (tid == 0) {
        // Detect mask storage: numpy bool (1 byte) vs int32 coercion.
        // For int32 0/1 values, bytes 1..3 of each word are zero; for packed
        // bools (~half ones) they are not. Scan first 64 words (256 entries).
        const unsigned int* w = (const unsigned int*)mask_raw;
        unsigned int acc = 0;
        for (int i = 0; i < 64; i++) acc |= w[i] & 0xFFFFFF00u;
        s_is_byte = (acc != 0u);
    }

    int q0 = blockIdx.x * 256 + tid;
    int q1 = q0 + 128;

    // Load the two query vectors as packed pairs (q0[c], q1[c])
    u64 qp2[DKQ];
    {
        const float* qr0 = d_qproj + ((size_t)b * LQ + q0) * DKQ;
        const float* qr1 = qr0 + 128 * DKQ;
        #pragma unroll
        for (int c = 0; c < DKQ; c++) qp2[c] = pack2(qr0[c], qr1[c]);
    }

    u64 o0[DIN / 2], o1[DIN / 2];
    #pragma unroll
    for (int i = 0; i < DIN / 2; i++) { o0[i] = 0ull; o1[i] = 0ull; }
    float l0 = 0.f, l1 = 0.f;

    const float* kbase = d_kproj + (size_t)b * LK * DKQ;
    const float* vbase = d_vproj + (size_t)b * LK * DIN;
    const unsigned char* mB = (const unsigned char*)mask_raw + (size_t)b * LK;
    const int*           mI = (const int*)mask_raw + (size_t)b * LK;

    for (int t0 = 0; t0 < LK; t0 += TS) {
        __syncthreads();   // previous tile fully consumed
        // cooperative tile load: K (duplicated), V, mask
        {
            const float* kg = kbase + (size_t)t0 * DKQ;
            for (int i = tid; i < TS * DKQ; i += 128) {
                int row = i / DKQ;
                int c   = i - row * DKQ;
                float v = kg[i];
                ks2[row * (2 * DKQ) + 2 * c]     = v;
                ks2[row * (2 * DKQ) + 2 * c + 1] = v;
            }
            const float4* vg  = (const float4*)(vbase + (size_t)t0 * DIN);
            float4*       vsh = (float4*)vs;
            for (int i = tid; i < TS * DIN / 4; i += 128) vsh[i] = vg[i];
            int mv = s_is_byte ? (int)mB[t0 + tid] : mI[t0 + tid];
            ms[tid] = mv ? 0.f : 1.f;   // True masks OUT
        }
        __syncthreads();

        #pragma unroll 2
        for (int j = 0; j < TS; j++) {
            const u64* kr = (const u64*)(ks2 + j * (2 * DKQ));
            u64 sA = 0ull, sB = 0ull;
            #pragma unroll
            for (int c = 0; c < DKQ / 2; c++) {
                sA = ffma2(qp2[2 * c],     kr[2 * c],     sA);
                sB = ffma2(qp2[2 * c + 1], kr[2 * c + 1], sB);
            }
            float2 a2 = unpack2(sA), b2 = unpack2(sB);
            float s0 = a2.x + b2.x;
            float s1 = a2.y + b2.y;
            float mf = ms[j];
            // scores bounded by sqrt(20): exp without max-subtraction is safe
            float e0 = mf * __expf(s0);
            float e1 = mf * __expf(s1);
            l0 += e0; l1 += e1;
            u64 e0p = pack2(e0, e0);
            u64 e1p = pack2(e1, e1);
            const u64* vr = (const u64*)(vs + j * DIN);
            #pragma unroll
            for (int i = 0; i < DIN / 2; i++) {
                u64 vv = vr[i];
                o0[i] = ffma2(e0p, vv, o0[i]);
                o1[i] = ffma2(e1p, vv, o1[i]);
            }
        }
    }

    // ---- epilogue: o/l + ques residual, LayerNorm over 32, store ----
    #pragma unroll
    for (int which = 0; which < 2; which++) {
        int   qi  = which == 0 ? q0 : q1;
        u64*  oa  = which == 0 ? o0 : o1;
        float l   = which == 0 ? l0 : l1;
        float invl = 1.f / l;

        float tv[DIN];
        {
            const float4* qv4 = (const float4*)(ques + ((size_t)b * LQ + qi) * DIN);
            #pragma unroll
            for (int i = 0; i < DIN / 2; i++) {
                float2 f = unpack2(oa[i]);
                tv[2 * i]     = f.x * invl;
                tv[2 * i + 1] = f.y * invl;
            }
            #pragma unroll
            for (int i = 0; i < 8; i++) {
                float4 t = qv4[i];
                tv[4*i] += t.x; tv[4*i+1] += t.y; tv[4*i+2] += t.z; tv[4*i+3] += t.w;
            }
        }
        float m = 0.f;
        #pragma unroll
        for (int c = 0; c < DIN; c++) m += tv[c];
        m *= (1.f / DIN);
        float v = 0.f;
        #pragma unroll
        for (int c = 0; c < DIN; c++) { float d = tv[c] - m; v += d * d; }
        v *= (1.f / DIN);
        float rs = rsqrtf(v + EPS);

        float4* po = (float4*)(out + ((size_t)b * LQ + qi) * DIN);
        #pragma unroll
        for (int i = 0; i < 8; i++) {
            float4 t;
            t.x = (tv[4*i]   - m) * rs * sgo[4*i]   + sbo[4*i];
            t.y = (tv[4*i+1] - m) * rs * sgo[4*i+1] + sbo[4*i+1];
            t.z = (tv[4*i+2] - m) * rs * sgo[4*i+2] + sbo[4*i+2];
            t.w = (tv[4*i+3] - m) * rs * sgo[4*i+3] + sbo[4*i+3];
            po[i] = t;
        }
    }
}

// ---------------------------------------------------------------------------
extern "C" void kernel_launch(void* const* d_in, const int* in_sizes, int n_in,
                              void* d_out, int out_size)
{
    const float* vals = (const float*)d_in[0];
    const float* keys = (const float*)d_in[1];
    const float* ques = (const float*)d_in[2];
    const void*  mask = d_in[3];
    const float* Wv   = (const float*)d_in[4];
    const float* Wk   = (const float*)d_in[5];
    const float* Wq   = (const float*)d_in[6];
    const float* gk   = (const float*)d_in[7];
    const float* bk   = (const float*)d_in[8];
    const float* gq   = (const float*)d_in[9];
    const float* bq   = (const float*)d_in[10];
    const float* go   = (const float*)d_in[11];
    const float* bo   = (const float*)d_in[12];
    float* out = (float*)d_out;

    proj_kernel<<<(NB * LK) / 256, 256>>>(vals, keys, ques, Wv, Wk, Wq, gk, bk, gq, bq);

    dim3 grid(LQ / 256, NB);
    attn_kernel<<<grid, 128>>>(mask, ques, go, bo, out);
}